// round 7
// baseline (speedup 1.0000x reference)
#include <cuda_runtime.h>
#include <cuda_bf16.h>
#include <cstdint>

#define Bb 4
#define Nn 4096
#define Dd 256
#define Mm (Bb*Nn)

__device__ float g_Q[Mm*Dd];
__device__ float g_K[Mm*Dd];
__device__ float g_V[Mm*Dd];
__device__ __nv_bfloat16 g_Qhi[Mm*Dd], g_Qlo[Mm*Dd];
__device__ __nv_bfloat16 g_Khi[Mm*Dd], g_Klo[Mm*Dd];
__device__ __nv_bfloat16 g_Vhi[Mm*Dd], g_Vlo[Mm*Dd];

// ---------------- f32x2 (qkv kernel) ----------------
__device__ __forceinline__ unsigned long long ffma2(unsigned long long a,
                                                    unsigned long long b,
                                                    unsigned long long c)
{ unsigned long long d;
  asm("fma.rn.f32x2 %0, %1, %2, %3;" : "=l"(d) : "l"(a), "l"(b), "l"(c));
  return d; }
__device__ __forceinline__ float2 unpack2(unsigned long long v)
{ float x, y; asm("mov.b64 {%0, %1}, %2;" : "=f"(x), "=f"(y) : "l"(v));
  return make_float2(x, y); }

// ---------------- mma.sync / ldmatrix / cp.async ----------------
__device__ __forceinline__ uint32_t smem_u32(const void* p)
{ uint32_t a;
  asm("{ .reg .u64 t; cvta.to.shared.u64 t, %1; cvt.u32.u64 %0, t; }":"=r"(a):"l"(p));
  return a; }

__device__ __forceinline__ void ldsm4(uint32_t* r, uint32_t a)
{ asm volatile("ldmatrix.sync.aligned.m8n8.x4.shared.b16 {%0,%1,%2,%3}, [%4];"
    : "=r"(r[0]), "=r"(r[1]), "=r"(r[2]), "=r"(r[3]) : "r"(a)); }
__device__ __forceinline__ void ldsm2(uint32_t* r, uint32_t a)
{ asm volatile("ldmatrix.sync.aligned.m8n8.x2.shared.b16 {%0,%1}, [%2];"
    : "=r"(r[0]), "=r"(r[1]) : "r"(a)); }
__device__ __forceinline__ void ldsm4t(uint32_t* r, uint32_t a)
{ asm volatile("ldmatrix.sync.aligned.m8n8.x4.trans.shared.b16 {%0,%1,%2,%3}, [%4];"
    : "=r"(r[0]), "=r"(r[1]), "=r"(r[2]), "=r"(r[3]) : "r"(a)); }

__device__ __forceinline__ void mma16816(float* c, const uint32_t* a, const uint32_t* b)
{ asm volatile("mma.sync.aligned.m16n8k16.row.col.f32.bf16.bf16.f32 "
    "{%0,%1,%2,%3}, {%4,%5,%6,%7}, {%8,%9}, {%0,%1,%2,%3};"
    : "+f"(c[0]), "+f"(c[1]), "+f"(c[2]), "+f"(c[3])
    : "r"(a[0]), "r"(a[1]), "r"(a[2]), "r"(a[3]), "r"(b[0]), "r"(b[1])); }

#define CPA16(d, s) asm volatile("cp.async.cg.shared.global [%0], [%1], 16;"::"r"(d),"l"(s))
#define CPCOMMIT()  asm volatile("cp.async.commit_group;":::"memory")
#define CPWAIT1()   asm volatile("cp.async.wait_group 1;":::"memory")

// swizzled blocked-atom layouts (Swizzle<3,4,3>, 128B rows)
#define SWZ(o) ((o) ^ (((o) >> 3) & 0x70))
__device__ __forceinline__ uint32_t qswz(int r, int cb)   // 64 rows x 512B
{ return SWZ((uint32_t)((((r>>3) + (cb>>7)*8)*1024) + (r&7)*128 + (cb&127))); }
__device__ __forceinline__ uint32_t kswz(int r, int cb)   // 32 rows x 512B
{ return SWZ((uint32_t)((((r>>3) + (cb>>7)*4)*1024) + (r&7)*128 + (cb&127))); }
__device__ __forceinline__ uint32_t pswz(int r, int cb)   // 128B rows
{ return SWZ((uint32_t)(r*128 + cb)); }

// SMEM map
#define SM_QH 0
#define SM_QL 32768
#define SM_ST 65536          // 2 stages x 64KB (Kh|Kl|Vh|Vl each 16KB)
#define SM_PH (65536 + 131072)
#define SM_PL (SM_PH + 8192)
#define SM_TOT (SM_PL + 8192)   // 212992 B

// ---------------------------------------------------------------------------
// QKV projection (fp32 f32x2 SIMT — known good)
// ---------------------------------------------------------------------------
__global__ __launch_bounds__(256, 1)
void qkv_kernel(const float* __restrict__ x,
                const float* __restrict__ Wq, const float* __restrict__ bq,
                const float* __restrict__ Wk, const float* __restrict__ bk,
                const float* __restrict__ Wv, const float* __restrict__ bv)
{
    const int z = blockIdx.z;
    const float* W    = (z == 0) ? Wq : (z == 1) ? Wk : Wv;
    const float* bias = (z == 0) ? bq : (z == 1) ? bk : bv;
    float* out        = (z == 0) ? g_Q : (z == 1) ? g_K : g_V;
    const int e0 = blockIdx.x * 64, m0 = blockIdx.y * 64;
    const int t = threadIdx.x, tx = t & 15, ty = t >> 4;
    __shared__ float Xs[64][36], Ws[64][36];
    unsigned long long acc2[4][4] = {};
    for (int k0 = 0; k0 < Dd; k0 += 32) {
        int row = t >> 3, col = (t & 7) * 4;
        #pragma unroll
        for (int rr = 0; rr < 2; rr++) {
            *(float4*)&Xs[row + rr*32][col] =
                *(const float4*)&x[(size_t)(m0 + row + rr*32)*Dd + k0 + col];
            *(float4*)&Ws[row + rr*32][col] =
                *(const float4*)&W[(size_t)(e0 + row + rr*32)*Dd + k0 + col];
        }
        __syncthreads();
        #pragma unroll
        for (int kk = 0; kk < 32; kk += 4) {
            ulonglong2 a2[4], b2[4];
            #pragma unroll
            for (int i = 0; i < 4; i++) a2[i] = *(const ulonglong2*)&Xs[ty + i*16][kk];
            #pragma unroll
            for (int j = 0; j < 4; j++) b2[j] = *(const ulonglong2*)&Ws[tx + j*16][kk];
            #pragma unroll
            for (int i = 0; i < 4; i++)
                #pragma unroll
                for (int j = 0; j < 4; j++) {
                    acc2[i][j] = ffma2(a2[i].x, b2[j].x, acc2[i][j]);
                    acc2[i][j] = ffma2(a2[i].y, b2[j].y, acc2[i][j]);
                }
        }
        __syncthreads();
    }
    #pragma unroll
    for (int j = 0; j < 4; j++) {
        float bb = bias[e0 + tx + j*16];
        #pragma unroll
        for (int i = 0; i < 4; i++) {
            float2 v = unpack2(acc2[i][j]);
            out[(size_t)(m0 + ty + i*16)*Dd + e0 + tx + j*16] = v.x + v.y + bb;
        }
    }
}

// fp32 -> bf16 hi/lo split, elementwise (Q, K, V)
__global__ __launch_bounds__(256, 4) void convA_kernel()
{
    const int z = blockIdx.y;
    const float* in = (z == 0) ? g_Q : (z == 1) ? g_K : g_V;
    __nv_bfloat16* hi = (z == 0) ? g_Qhi : (z == 1) ? g_Khi : g_Vhi;
    __nv_bfloat16* lo = (z == 0) ? g_Qlo : (z == 1) ? g_Klo : g_Vlo;
    size_t i = (size_t)(blockIdx.x * 256 + threadIdx.x) * 4;
    float4 v = *(const float4*)&in[i];
    float a[4] = {v.x, v.y, v.z, v.w};
    ushort h[4], l[4];
    #pragma unroll
    for (int k = 0; k < 4; k++) {
        __nv_bfloat16 hb = __float2bfloat16(a[k]);
        h[k] = __bfloat16_as_ushort(hb);
        l[k] = __bfloat16_as_ushort(__float2bfloat16(a[k] - __bfloat162float(hb)));
    }
    *(uint2*)&hi[i] = make_uint2(h[0] | ((uint32_t)h[1]<<16), h[2] | ((uint32_t)h[3]<<16));
    *(uint2*)&lo[i] = make_uint2(l[0] | ((uint32_t)l[1]<<16), l[2] | ((uint32_t)l[3]<<16));
}

// ---------------------------------------------------------------------------
// HMMA flash attention v2: 512 thr = 16 warps (4 row x 4 col), Br=64, Bc=32.
// S: warp = 16 rows x 8 keys (ldsm.x2 B-frags). PV: warp = 16 rows x 64 cols.
// ---------------------------------------------------------------------------
__global__ __launch_bounds__(512, 1)
void attn_kernel(const int* __restrict__ mask, float* __restrict__ out)
{
    extern __shared__ char sm[];
    uint32_t sb = smem_u32(sm);
    const int t = threadIdx.x, lane = t & 31, wid = t >> 5;
    const int rw = wid >> 2, cw = wid & 3;
    const int b = blockIdx.y, q0 = blockIdx.x * 64;
    const int g = lane >> 2, tq = lane & 3;
    const int lrow = lane & 15, lk16 = (lane >> 4) * 16;

    // Q hi/lo -> smem (blocked swizzled), 2048 chunks each
    {
        const char* qh = (const char*)&g_Qhi[(size_t)(b*Nn + q0)*Dd];
        const char* ql = (const char*)&g_Qlo[(size_t)(b*Nn + q0)*Dd];
        #pragma unroll
        for (int i = 0; i < 4; i++) {
            int id = i*512 + t;
            int row = id >> 5, cb = (id & 31) * 16;
            uint32_t o = qswz(row, cb);
            *(uint4*)(sm + SM_QH + o) = *(const uint4*)(qh + (size_t)row*512 + cb);
            *(uint4*)(sm + SM_QL + o) = *(const uint4*)(ql + (size_t)row*512 + cb);
        }
    }

    const char* baseKh = (const char*)&g_Khi[(size_t)(b*Nn)*Dd];
    const char* baseKl = (const char*)&g_Klo[(size_t)(b*Nn)*Dd];
    const char* baseVh = (const char*)&g_Vhi[(size_t)(b*Nn)*Dd];
    const char* baseVl = (const char*)&g_Vlo[(size_t)(b*Nn)*Dd];
    auto issue = [&](int jt) {
        uint32_t stg = sb + SM_ST + (jt & 1) * 65536;
        size_t gb = (size_t)(jt * 32) * 512;
        const char* srcs[4] = { baseKh + gb, baseKl + gb, baseVh + gb, baseVl + gb };
        #pragma unroll
        for (int a = 0; a < 4; a++) {
            #pragma unroll
            for (int i = 0; i < 2; i++) {
                int id = i*512 + t;       // 1024 chunks per array
                int row = id >> 5, cb = (id & 31) * 16;
                CPA16(stg + a*16384 + kswz(row, cb), srcs[a] + (size_t)row*512 + cb);
            }
        }
    };
    issue(0); CPCOMMIT();
    issue(1); CPCOMMIT();
    __syncthreads();   // Q visible

    float l0 = 0.f, l1 = 0.f;
    float o[8][4] = {};

    // S-phase B-frag address (lanes 0-15 meaningful for ldsm.x2)
    const int skey = 8*cw + (lane & 7);
    const int skb  = ((lane >> 3) & 1) * 16;
    // PV V-frag row pattern
    const int vr = (lane & 7) + ((lane >> 3) & 1) * 8;

    for (int j = 0; j < 128; j++) {
        CPWAIT1();
        __syncthreads();
        uint32_t stg = sb + SM_ST + (j & 1) * 65536;
        uint32_t sKh = stg, sKl = stg + 16384, sVh = stg + 32768, sVl = stg + 49152;

        // mask prefetch: rows (16rw+g, +8) x keys (8cw+2tq, +1)
        const int j0 = j * 32;
        const int* mrow = mask + (size_t)(b*Nn + q0 + 16*rw + g) * Nn + j0 + 8*cw + 2*tq;
        int2 m0 = *(const int2*)mrow;
        int2 m1 = *(const int2*)(mrow + 8*Nn);

        // ---- S = Q K^T (3-term split): 16 rows x 8 keys ----
        float sa[4] = {};
        #pragma unroll
        for (int ks = 0; ks < 16; ks++) {
            uint32_t aqh[4], aql[4], bk[2], bl[2];
            uint32_t qo = qswz(16*rw + lrow, ks*32 + lk16);
            ldsm4(aqh, sb + SM_QH + qo);
            ldsm4(aql, sb + SM_QL + qo);
            uint32_t ko = kswz(skey, ks*32 + skb);
            ldsm2(bk, sKh + ko);
            ldsm2(bl, sKl + ko);
            mma16816(sa, aqh, bk);
            mma16816(sa, aqh, bl);
            mma16816(sa, aql, bk);
        }

        // ---- softmax (no-max) + P bf16 split -> smem ----
        {
            const float sc = 0.0625f;
            float p0 = m0.x ? __expf(sa[0]*sc) : 0.f;
            float p1 = m0.y ? __expf(sa[1]*sc) : 0.f;
            float p2 = m1.x ? __expf(sa[2]*sc) : 0.f;
            float p3 = m1.y ? __expf(sa[3]*sc) : 0.f;
            l0 += p0 + p1;
            l1 += p2 + p3;
            __nv_bfloat16 h0 = __float2bfloat16(p0), h1 = __float2bfloat16(p1);
            __nv_bfloat16 h2 = __float2bfloat16(p2), h3 = __float2bfloat16(p3);
            uint32_t phT = __bfloat16_as_ushort(h0) | ((uint32_t)__bfloat16_as_ushort(h1) << 16);
            uint32_t phB = __bfloat16_as_ushort(h2) | ((uint32_t)__bfloat16_as_ushort(h3) << 16);
            ushort s0 = __bfloat16_as_ushort(__float2bfloat16(p0 - __bfloat162float(h0)));
            ushort s1 = __bfloat16_as_ushort(__float2bfloat16(p1 - __bfloat162float(h1)));
            ushort s2 = __bfloat16_as_ushort(__float2bfloat16(p2 - __bfloat162float(h2)));
            ushort s3 = __bfloat16_as_ushort(__float2bfloat16(p3 - __bfloat162float(h3)));
            uint32_t plT = s0 | ((uint32_t)s1 << 16);
            uint32_t plB = s2 | ((uint32_t)s3 << 16);
            int cb = (8*cw + 2*tq) * 2;
            int row0 = 16*rw + g;
            *(uint32_t*)(sm + SM_PH + pswz(row0,     cb)) = phT;
            *(uint32_t*)(sm + SM_PH + pswz(row0 + 8, cb)) = phB;
            *(uint32_t*)(sm + SM_PL + pswz(row0,     cb)) = plT;
            *(uint32_t*)(sm + SM_PL + pswz(row0 + 8, cb)) = plB;
        }
        __syncthreads();

        // ---- O += P V (full k=32; warp = 16 rows x 64 d-cols) ----
        #pragma unroll
        for (int ks = 0; ks < 2; ks++) {
            uint32_t aph[4], apl[4];
            uint32_t po = pswz(16*rw + lrow, ks*32 + lk16);
            ldsm4(aph, sb + SM_PH + po);
            ldsm4(apl, sb + SM_PL + po);
            #pragma unroll
            for (int n2 = 0; n2 < 4; n2++) {
                int vcb = (64*cw + n2*16 + (lane >> 4)*8) * 2;
                uint32_t vo = kswz(ks*16 + vr, vcb);
                uint32_t bvh[4], bvl[4];
                ldsm4t(bvh, sVh + vo);
                ldsm4t(bvl, sVl + vo);
                mma16816(o[n2*2],   aph, bvh);
                mma16816(o[n2*2],   aph, bvl);
                mma16816(o[n2*2],   apl, bvh);
                mma16816(o[n2*2+1], aph, bvh + 2);
                mma16816(o[n2*2+1], aph, bvl + 2);
                mma16816(o[n2*2+1], apl, bvh + 2);
            }
        }
        __syncthreads();
        if (j + 2 < 128) issue(j + 2);
        CPCOMMIT();
    }

    // ---- epilogue: l reduce (quad + 4 cw partials), scale, store ----
    l0 += __shfl_xor_sync(0xffffffffu, l0, 1);
    l0 += __shfl_xor_sync(0xffffffffu, l0, 2);
    l1 += __shfl_xor_sync(0xffffffffu, l1, 1);
    l1 += __shfl_xor_sync(0xffffffffu, l1, 2);
    float* Ls = (float*)(sm + SM_PH);   // P dead (synced after last PV)
    if (tq == 0) {
        Ls[cw*64 + 16*rw + g]     = l0;
        Ls[cw*64 + 16*rw + 8 + g] = l1;
    }
    __syncthreads();
    int r0 = 16*rw + g;
    float inv0 = 1.0f / (Ls[r0] + Ls[64 + r0] + Ls[128 + r0] + Ls[192 + r0]);
    float inv1 = 1.0f / (Ls[r0+8] + Ls[64 + r0+8] + Ls[128 + r0+8] + Ls[192 + r0+8]);
    size_t row0 = (size_t)(b*Nn + q0 + r0);
    #pragma unroll
    for (int nt = 0; nt < 8; nt++) {
        int col = 64*cw + nt*8 + 2*tq;
        *(float2*)&out[row0*Dd + col]       = make_float2(o[nt][0]*inv0, o[nt][1]*inv0);
        *(float2*)&out[(row0 + 8)*Dd + col] = make_float2(o[nt][2]*inv1, o[nt][3]*inv1);
    }
}

extern "C" void kernel_launch(void* const* d_in, const int* in_sizes, int n_in,
                              void* d_out, int out_size)
{
    const float* x    = (const float*)d_in[0];
    const int*   mask = (const int*)  d_in[1];
    const float* Wq   = (const float*)d_in[2];
    const float* bq   = (const float*)d_in[3];
    const float* Wk   = (const float*)d_in[4];
    const float* bk   = (const float*)d_in[5];
    const float* Wv   = (const float*)d_in[6];
    const float* bv   = (const float*)d_in[7];
    float* out = (float*)d_out;

    cudaFuncSetAttribute(attn_kernel,
                         cudaFuncAttributeMaxDynamicSharedMemorySize, SM_TOT);

    dim3 g1(Dd/64, Mm/64, 3);
    qkv_kernel<<<g1, 256>>>(x, Wq, bq, Wk, bk, Wv, bv);
    dim3 gA(Mm*Dd/1024, 3);
    convA_kernel<<<gA, 256>>>();
    dim3 g2(Nn/64, Bb);
    attn_kernel<<<g2, 512, SM_TOT>>>(mask, out);
}

// round 8
// speedup vs baseline: 1.1752x; 1.1752x over previous
#include <cuda_runtime.h>
#include <cuda_bf16.h>
#include <cstdint>

#define Bb 4
#define Nn 4096
#define Dd 256
#define Mm (Bb*Nn)

__device__ float g_Q[Mm*Dd];
__device__ float g_K[Mm*Dd];
__device__ float g_V[Mm*Dd];
__device__ __nv_bfloat16 g_Qhi[Mm*Dd], g_Qlo[Mm*Dd];
__device__ __nv_bfloat16 g_Khi[Mm*Dd], g_Klo[Mm*Dd];
__device__ __nv_bfloat16 g_Vhi[Mm*Dd], g_Vlo[Mm*Dd];

// ---------------- f32x2 (qkv kernel) ----------------
__device__ __forceinline__ unsigned long long ffma2(unsigned long long a,
                                                    unsigned long long b,
                                                    unsigned long long c)
{ unsigned long long d;
  asm("fma.rn.f32x2 %0, %1, %2, %3;" : "=l"(d) : "l"(a), "l"(b), "l"(c));
  return d; }
__device__ __forceinline__ float2 unpack2(unsigned long long v)
{ float x, y; asm("mov.b64 {%0, %1}, %2;" : "=f"(x), "=f"(y) : "l"(v));
  return make_float2(x, y); }

// ---------------- mma.sync / ldmatrix / cp.async ----------------
__device__ __forceinline__ uint32_t smem_u32(const void* p)
{ uint32_t a;
  asm("{ .reg .u64 t; cvta.to.shared.u64 t, %1; cvt.u32.u64 %0, t; }":"=r"(a):"l"(p));
  return a; }

__device__ __forceinline__ void ldsm4(uint32_t* r, uint32_t a)
{ asm volatile("ldmatrix.sync.aligned.m8n8.x4.shared.b16 {%0,%1,%2,%3}, [%4];"
    : "=r"(r[0]), "=r"(r[1]), "=r"(r[2]), "=r"(r[3]) : "r"(a)); }
__device__ __forceinline__ void ldsm4t(uint32_t* r, uint32_t a)
{ asm volatile("ldmatrix.sync.aligned.m8n8.x4.trans.shared.b16 {%0,%1,%2,%3}, [%4];"
    : "=r"(r[0]), "=r"(r[1]), "=r"(r[2]), "=r"(r[3]) : "r"(a)); }

__device__ __forceinline__ void mma16816(float* c, const uint32_t* a, const uint32_t* b)
{ asm volatile("mma.sync.aligned.m16n8k16.row.col.f32.bf16.bf16.f32 "
    "{%0,%1,%2,%3}, {%4,%5,%6,%7}, {%8,%9}, {%0,%1,%2,%3};"
    : "+f"(c[0]), "+f"(c[1]), "+f"(c[2]), "+f"(c[3])
    : "r"(a[0]), "r"(a[1]), "r"(a[2]), "r"(a[3]), "r"(b[0]), "r"(b[1])); }

#define CPA16(d, s) asm volatile("cp.async.cg.shared.global [%0], [%1], 16;"::"r"(d),"l"(s))
#define CPCOMMIT()  asm volatile("cp.async.commit_group;":::"memory")
#define CPWAIT1()   asm volatile("cp.async.wait_group 1;":::"memory")

// swizzled blocked-atom layouts (Swizzle<3,4,3>, 128B rows)
#define SWZ(o) ((o) ^ (((o) >> 3) & 0x70))
__device__ __forceinline__ uint32_t qswz(int r, int cb)   // 64 rows x 512B
{ return SWZ((uint32_t)((((r>>3) + (cb>>7)*8)*1024) + (r&7)*128 + (cb&127))); }
__device__ __forceinline__ uint32_t kswz(int r, int cb)   // 32 rows x 512B
{ return SWZ((uint32_t)((((r>>3) + (cb>>7)*4)*1024) + (r&7)*128 + (cb&127))); }
__device__ __forceinline__ uint32_t pswz(int r, int cb)   // 128B rows
{ return SWZ((uint32_t)(r*128 + cb)); }

// SMEM map
#define SM_QH 0
#define SM_QL 32768
#define SM_ST 65536            // 2 stages x 64KB (Kh|Kl|Vh|Vl each 16KB)
#define SM_PH (65536 + 131072) // P hi only (Plo term dropped)
#define SM_TOT (SM_PH + 8192)  // 204800 B

// ---------------------------------------------------------------------------
// QKV projection (fp32 f32x2 SIMT — known good)
// ---------------------------------------------------------------------------
__global__ __launch_bounds__(256, 1)
void qkv_kernel(const float* __restrict__ x,
                const float* __restrict__ Wq, const float* __restrict__ bq,
                const float* __restrict__ Wk, const float* __restrict__ bk,
                const float* __restrict__ Wv, const float* __restrict__ bv)
{
    const int z = blockIdx.z;
    const float* W    = (z == 0) ? Wq : (z == 1) ? Wk : Wv;
    const float* bias = (z == 0) ? bq : (z == 1) ? bk : bv;
    float* out        = (z == 0) ? g_Q : (z == 1) ? g_K : g_V;
    const int e0 = blockIdx.x * 64, m0 = blockIdx.y * 64;
    const int t = threadIdx.x, tx = t & 15, ty = t >> 4;
    __shared__ float Xs[64][36], Ws[64][36];
    unsigned long long acc2[4][4] = {};
    for (int k0 = 0; k0 < Dd; k0 += 32) {
        int row = t >> 3, col = (t & 7) * 4;
        #pragma unroll
        for (int rr = 0; rr < 2; rr++) {
            *(float4*)&Xs[row + rr*32][col] =
                *(const float4*)&x[(size_t)(m0 + row + rr*32)*Dd + k0 + col];
            *(float4*)&Ws[row + rr*32][col] =
                *(const float4*)&W[(size_t)(e0 + row + rr*32)*Dd + k0 + col];
        }
        __syncthreads();
        #pragma unroll
        for (int kk = 0; kk < 32; kk += 4) {
            ulonglong2 a2[4], b2[4];
            #pragma unroll
            for (int i = 0; i < 4; i++) a2[i] = *(const ulonglong2*)&Xs[ty + i*16][kk];
            #pragma unroll
            for (int j = 0; j < 4; j++) b2[j] = *(const ulonglong2*)&Ws[tx + j*16][kk];
            #pragma unroll
            for (int i = 0; i < 4; i++)
                #pragma unroll
                for (int j = 0; j < 4; j++) {
                    acc2[i][j] = ffma2(a2[i].x, b2[j].x, acc2[i][j]);
                    acc2[i][j] = ffma2(a2[i].y, b2[j].y, acc2[i][j]);
                }
        }
        __syncthreads();
    }
    #pragma unroll
    for (int j = 0; j < 4; j++) {
        float bb = bias[e0 + tx + j*16];
        #pragma unroll
        for (int i = 0; i < 4; i++) {
            float2 v = unpack2(acc2[i][j]);
            out[(size_t)(m0 + ty + i*16)*Dd + e0 + tx + j*16] = v.x + v.y + bb;
        }
    }
}

// fp32 -> bf16 hi/lo split, elementwise (Q, K, V)
__global__ __launch_bounds__(256, 4) void convA_kernel()
{
    const int z = blockIdx.y;
    const float* in = (z == 0) ? g_Q : (z == 1) ? g_K : g_V;
    __nv_bfloat16* hi = (z == 0) ? g_Qhi : (z == 1) ? g_Khi : g_Vhi;
    __nv_bfloat16* lo = (z == 0) ? g_Qlo : (z == 1) ? g_Klo : g_Vlo;
    size_t i = (size_t)(blockIdx.x * 256 + threadIdx.x) * 4;
    float4 v = *(const float4*)&in[i];
    float a[4] = {v.x, v.y, v.z, v.w};
    ushort h[4], l[4];
    #pragma unroll
    for (int k = 0; k < 4; k++) {
        __nv_bfloat16 hb = __float2bfloat16(a[k]);
        h[k] = __bfloat16_as_ushort(hb);
        l[k] = __bfloat16_as_ushort(__float2bfloat16(a[k] - __bfloat162float(hb)));
    }
    *(uint2*)&hi[i] = make_uint2(h[0] | ((uint32_t)h[1]<<16), h[2] | ((uint32_t)h[3]<<16));
    *(uint2*)&lo[i] = make_uint2(l[0] | ((uint32_t)l[1]<<16), l[2] | ((uint32_t)l[3]<<16));
}

// ---------------------------------------------------------------------------
// HMMA flash attention v3: 256 thr (4 row x 2 col warps), Br=64, Bc=32.
// Split-term S accumulators (6 independent MMA chains); PV = Ph(Vh+Vl).
// ---------------------------------------------------------------------------
__global__ __launch_bounds__(256, 1)
void attn_kernel(const int* __restrict__ mask, float* __restrict__ out)
{
    extern __shared__ char sm[];
    uint32_t sb = smem_u32(sm);
    const int t = threadIdx.x, lane = t & 31, wid = t >> 5;
    const int r = wid & 3, cw = wid >> 2;
    const int b = blockIdx.y, q0 = blockIdx.x * 64;
    const int g = lane >> 2, tq = lane & 3;
    const int lrow = lane & 15, lk16 = (lane >> 4) * 16;

    // Q hi/lo -> smem (blocked swizzled)
    {
        const char* qh = (const char*)&g_Qhi[(size_t)(b*Nn + q0)*Dd];
        const char* ql = (const char*)&g_Qlo[(size_t)(b*Nn + q0)*Dd];
        #pragma unroll
        for (int i = 0; i < 8; i++) {
            int id = i*256 + t;           // 2048 16B chunks
            int row = id >> 5, cb = (id & 31) * 16;
            uint32_t o = qswz(row, cb);
            *(uint4*)(sm + SM_QH + o) = *(const uint4*)(qh + (size_t)row*512 + cb);
            *(uint4*)(sm + SM_QL + o) = *(const uint4*)(ql + (size_t)row*512 + cb);
        }
    }

    const char* baseKh = (const char*)&g_Khi[(size_t)(b*Nn)*Dd];
    const char* baseKl = (const char*)&g_Klo[(size_t)(b*Nn)*Dd];
    const char* baseVh = (const char*)&g_Vhi[(size_t)(b*Nn)*Dd];
    const char* baseVl = (const char*)&g_Vlo[(size_t)(b*Nn)*Dd];
    auto issue = [&](int jt) {
        uint32_t stg = sb + SM_ST + (jt & 1) * 65536;
        size_t gb = (size_t)(jt * 32) * 512;
        const char* srcs[4] = { baseKh + gb, baseKl + gb, baseVh + gb, baseVl + gb };
        #pragma unroll
        for (int a = 0; a < 4; a++) {
            #pragma unroll
            for (int i = 0; i < 4; i++) {
                int id = i*256 + t;       // 1024 chunks per array
                int row = id >> 5, cb = (id & 31) * 16;
                CPA16(stg + a*16384 + kswz(row, cb), srcs[a] + (size_t)row*512 + cb);
            }
        }
    };
    issue(0); CPCOMMIT();
    issue(1); CPCOMMIT();
    __syncthreads();   // Q visible

    float l0 = 0.f, l1 = 0.f;
    float o[16][4] = {};

    for (int j = 0; j < 128; j++) {
        CPWAIT1();
        __syncthreads();
        uint32_t stg = sb + SM_ST + (j & 1) * 65536;
        uint32_t sKh = stg, sKl = stg + 16384, sVh = stg + 32768, sVl = stg + 49152;

        // mask prefetch (consumed after S MMAs)
        const int j0 = j * 32;
        const int* mrow = mask + (size_t)(b*Nn + q0 + 16*r + g) * Nn + j0 + 16*cw + 2*tq;
        int2 mA0 = *(const int2*)mrow;
        int2 mA1 = *(const int2*)(mrow + 8);
        int2 mB0 = *(const int2*)(mrow + 8*Nn);
        int2 mB1 = *(const int2*)(mrow + 8*Nn + 8);

        // ---- S = Q K^T, 3-term split with SEPARATE accumulators ----
        float s_hh[2][4] = {}, s_hl[2][4] = {}, s_lh[2][4] = {};
        const int key = 16*cw + (lane >> 4)*8 + (lane & 7);
        const int kb16 = ((lane >> 3) & 1) * 16;
        #pragma unroll
        for (int ks = 0; ks < 16; ks++) {
            uint32_t aqh[4], aql[4], bk[4], bl[4];
            uint32_t qo = ks*32 + lk16;
            ldsm4(aqh, sb + SM_QH + qswz(16*r + lrow, qo));
            ldsm4(aql, sb + SM_QL + qswz(16*r + lrow, qo));
            uint32_t ko = kswz(key, ks*32 + kb16);
            ldsm4(bk, sKh + ko);
            ldsm4(bl, sKl + ko);
            mma16816(s_hh[0], aqh, bk);
            mma16816(s_hl[0], aqh, bl);
            mma16816(s_lh[0], aql, bk);
            mma16816(s_hh[1], aqh, bk + 2);
            mma16816(s_hl[1], aqh, bl + 2);
            mma16816(s_lh[1], aql, bk + 2);
        }
        float sa[2][4];
        #pragma unroll
        for (int h = 0; h < 2; h++)
            #pragma unroll
            for (int e = 0; e < 4; e++)
                sa[h][e] = s_hh[h][e] + s_hl[h][e] + s_lh[h][e];

        // ---- softmax (no-max) + P hi -> smem ----
        {
            const float sc = 0.0625f;
            float p00 = mA0.x ? __expf(sa[0][0]*sc) : 0.f;
            float p01 = mA0.y ? __expf(sa[0][1]*sc) : 0.f;
            float p02 = mB0.x ? __expf(sa[0][2]*sc) : 0.f;
            float p03 = mB0.y ? __expf(sa[0][3]*sc) : 0.f;
            float p10 = mA1.x ? __expf(sa[1][0]*sc) : 0.f;
            float p11 = mA1.y ? __expf(sa[1][1]*sc) : 0.f;
            float p12 = mB1.x ? __expf(sa[1][2]*sc) : 0.f;
            float p13 = mB1.y ? __expf(sa[1][3]*sc) : 0.f;
            l0 += p00 + p01 + p10 + p11;
            l1 += p02 + p03 + p12 + p13;
            int colb = (16*cw + 2*tq) * 2;
            int row0 = 16*r + g;
            #pragma unroll
            for (int nt = 0; nt < 2; nt++) {
                float pa = nt ? p10 : p00, pb = nt ? p11 : p01;
                float pc = nt ? p12 : p02, pd = nt ? p13 : p03;
                uint32_t phT = __bfloat16_as_ushort(__float2bfloat16(pa))
                             | ((uint32_t)__bfloat16_as_ushort(__float2bfloat16(pb)) << 16);
                uint32_t phB = __bfloat16_as_ushort(__float2bfloat16(pc))
                             | ((uint32_t)__bfloat16_as_ushort(__float2bfloat16(pd)) << 16);
                int cb2 = colb + nt*16;
                *(uint32_t*)(sm + SM_PH + pswz(row0,     cb2)) = phT;
                *(uint32_t*)(sm + SM_PH + pswz(row0 + 8, cb2)) = phB;
            }
        }
        __syncthreads();

        // ---- O += Ph (Vh + Vl), full k=32; warp = 16 rows x 128 d ----
        const int vr = (lane & 7) + ((lane >> 3) & 1) * 8;
        #pragma unroll
        for (int ks = 0; ks < 2; ks++) {
            uint32_t aph[4];
            ldsm4(aph, sb + SM_PH + pswz(16*r + lrow, ks*32 + lk16));
            #pragma unroll
            for (int n2 = 0; n2 < 8; n2++) {
                int vcb = (128*cw + n2*16 + (lane >> 4)*8) * 2;
                uint32_t vo = kswz(ks*16 + vr, vcb);
                uint32_t bvh[4], bvl[4];
                ldsm4t(bvh, sVh + vo);
                ldsm4t(bvl, sVl + vo);
                mma16816(o[n2*2],   aph, bvh);
                mma16816(o[n2*2],   aph, bvl);
                mma16816(o[n2*2+1], aph, bvh + 2);
                mma16816(o[n2*2+1], aph, bvl + 2);
            }
        }
        __syncthreads();
        if (j + 2 < 128) issue(j + 2);
        CPCOMMIT();
    }

    // ---- epilogue: l reduce (quad + col-warp pair), scale, store ----
    l0 += __shfl_xor_sync(0xffffffffu, l0, 1);
    l0 += __shfl_xor_sync(0xffffffffu, l0, 2);
    l1 += __shfl_xor_sync(0xffffffffu, l1, 1);
    l1 += __shfl_xor_sync(0xffffffffu, l1, 2);
    float* Ls = (float*)(sm + SM_PH);   // P dead after last PV (synced)
    if (tq == 0) {
        Ls[cw*64 + 16*r + g]     = l0;
        Ls[cw*64 + 16*r + 8 + g] = l1;
    }
    __syncthreads();
    float inv0 = 1.0f / (Ls[16*r + g]     + Ls[64 + 16*r + g]);
    float inv1 = 1.0f / (Ls[16*r + 8 + g] + Ls[64 + 16*r + 8 + g]);
    size_t row0 = (size_t)(b*Nn + q0 + 16*r + g);
    #pragma unroll
    for (int nt = 0; nt < 16; nt++) {
        int col = 128*cw + nt*8 + 2*tq;
        *(float2*)&out[row0*Dd + col]       = make_float2(o[nt][0]*inv0, o[nt][1]*inv0);
        *(float2*)&out[(row0 + 8)*Dd + col] = make_float2(o[nt][2]*inv1, o[nt][3]*inv1);
    }
}

extern "C" void kernel_launch(void* const* d_in, const int* in_sizes, int n_in,
                              void* d_out, int out_size)
{
    const float* x    = (const float*)d_in[0];
    const int*   mask = (const int*)  d_in[1];
    const float* Wq   = (const float*)d_in[2];
    const float* bq   = (const float*)d_in[3];
    const float* Wk   = (const float*)d_in[4];
    const float* bk   = (const float*)d_in[5];
    const float* Wv   = (const float*)d_in[6];
    const float* bv   = (const float*)d_in[7];
    float* out = (float*)d_out;

    cudaFuncSetAttribute(attn_kernel,
                         cudaFuncAttributeMaxDynamicSharedMemorySize, SM_TOT);

    dim3 g1(Dd/64, Mm/64, 3);
    qkv_kernel<<<g1, 256>>>(x, Wq, bq, Wk, bk, Wv, bv);
    dim3 gA(Mm*Dd/1024, 3);
    convA_kernel<<<gA, 256>>>();
    dim3 g2(Nn/64, Bb);
    attn_kernel<<<g2, 256, SM_TOT>>>(mask, out);
}

// round 9
// speedup vs baseline: 1.3346x; 1.1356x over previous
#include <cuda_runtime.h>
#include <cuda_bf16.h>
#include <cstdint>

#define Bb 4
#define Nn 4096
#define Dd 256
#define Mm (Bb*Nn)

__device__ __nv_bfloat16 g_xhi[Mm*Dd], g_xlo[Mm*Dd];
__device__ __nv_bfloat16 g_Whi[3*Dd*Dd], g_Wlo[3*Dd*Dd];
__device__ __nv_bfloat16 g_Qhi[Mm*Dd], g_Qlo[Mm*Dd];
__device__ __nv_bfloat16 g_Khi[Mm*Dd], g_Klo[Mm*Dd];
__device__ __nv_bfloat16 g_Vhi[Mm*Dd], g_Vlo[Mm*Dd];

// ---------------- mma.sync / ldmatrix / cp.async ----------------
__device__ __forceinline__ uint32_t smem_u32(const void* p)
{ uint32_t a;
  asm("{ .reg .u64 t; cvta.to.shared.u64 t, %1; cvt.u32.u64 %0, t; }":"=r"(a):"l"(p));
  return a; }

__device__ __forceinline__ void ldsm4(uint32_t* r, uint32_t a)
{ asm volatile("ldmatrix.sync.aligned.m8n8.x4.shared.b16 {%0,%1,%2,%3}, [%4];"
    : "=r"(r[0]), "=r"(r[1]), "=r"(r[2]), "=r"(r[3]) : "r"(a)); }
__device__ __forceinline__ void ldsm4t(uint32_t* r, uint32_t a)
{ asm volatile("ldmatrix.sync.aligned.m8n8.x4.trans.shared.b16 {%0,%1,%2,%3}, [%4];"
    : "=r"(r[0]), "=r"(r[1]), "=r"(r[2]), "=r"(r[3]) : "r"(a)); }

__device__ __forceinline__ void mma16816(float* c, const uint32_t* a, const uint32_t* b)
{ asm volatile("mma.sync.aligned.m16n8k16.row.col.f32.bf16.bf16.f32 "
    "{%0,%1,%2,%3}, {%4,%5,%6,%7}, {%8,%9}, {%0,%1,%2,%3};"
    : "+f"(c[0]), "+f"(c[1]), "+f"(c[2]), "+f"(c[3])
    : "r"(a[0]), "r"(a[1]), "r"(a[2]), "r"(a[3]), "r"(b[0]), "r"(b[1])); }

#define CPA16(d, s) asm volatile("cp.async.cg.shared.global [%0], [%1], 16;"::"r"(d),"l"(s))
#define CPCOMMIT()  asm volatile("cp.async.commit_group;":::"memory")
#define CPWAIT1()   asm volatile("cp.async.wait_group 1;":::"memory")

// swizzled blocked-atom layouts (Swizzle<3,4,3>, 128B rows)
#define SWZ(o) ((o) ^ (((o) >> 3) & 0x70))
__device__ __forceinline__ uint32_t xswz(int r, int cb)   // 128 rows x 512B
{ return SWZ((uint32_t)((((r>>3) + (cb>>7)*16)*1024) + (r&7)*128 + (cb&127))); }
__device__ __forceinline__ uint32_t qswz(int r, int cb)   // 64 rows x 512B
{ return SWZ((uint32_t)((((r>>3) + (cb>>7)*8)*1024) + (r&7)*128 + (cb&127))); }
__device__ __forceinline__ uint32_t kswz(int r, int cb)   // 32 rows x 512B
{ return SWZ((uint32_t)((((r>>3) + (cb>>7)*4)*1024) + (r&7)*128 + (cb&127))); }
__device__ __forceinline__ uint32_t pswz(int r, int cb)   // 128B rows
{ return SWZ((uint32_t)(r*128 + cb)); }

// attention SMEM map
#define SM_QH 0
#define SM_QL 32768
#define SM_ST 65536            // 2 stages x 64KB (Kh|Kl|Vh|Vl each 16KB)
#define SM_PH (65536 + 131072) // P hi only
#define SM_TOT (SM_PH + 8192)  // 204800 B

// qkvmm SMEM map
#define SMX_H 0
#define SMX_L 65536
#define SMW_H 131072
#define SMW_L 163840
#define SM_QKV_TOT 196608

// ---------------------------------------------------------------------------
// convX: split x fp32 -> bf16 hi/lo
// ---------------------------------------------------------------------------
__global__ __launch_bounds__(256, 4) void convX_kernel(const float* __restrict__ x)
{
    size_t i = (size_t)(blockIdx.x * 256 + threadIdx.x) * 4;
    float4 v = *(const float4*)&x[i];
    float a[4] = {v.x, v.y, v.z, v.w};
    ushort h[4], l[4];
    #pragma unroll
    for (int k = 0; k < 4; k++) {
        __nv_bfloat16 hb = __float2bfloat16(a[k]);
        h[k] = __bfloat16_as_ushort(hb);
        l[k] = __bfloat16_as_ushort(__float2bfloat16(a[k] - __bfloat162float(hb)));
    }
    *(uint2*)&g_xhi[i] = make_uint2(h[0] | ((uint32_t)h[1]<<16), h[2] | ((uint32_t)h[3]<<16));
    *(uint2*)&g_xlo[i] = make_uint2(l[0] | ((uint32_t)l[1]<<16), l[2] | ((uint32_t)l[3]<<16));
}

// convW: split the three weight matrices fp32 -> bf16 hi/lo
__global__ __launch_bounds__(256, 4)
void convW_kernel(const float* __restrict__ Wq, const float* __restrict__ Wk,
                  const float* __restrict__ Wv)
{
    const int z = blockIdx.y;
    const float* in = (z == 0) ? Wq : (z == 1) ? Wk : Wv;
    size_t base = (size_t)z * Dd * Dd;
    size_t i = (size_t)(blockIdx.x * 256 + threadIdx.x) * 4;
    float4 v = *(const float4*)&in[i];
    float a[4] = {v.x, v.y, v.z, v.w};
    ushort h[4], l[4];
    #pragma unroll
    for (int k = 0; k < 4; k++) {
        __nv_bfloat16 hb = __float2bfloat16(a[k]);
        h[k] = __bfloat16_as_ushort(hb);
        l[k] = __bfloat16_as_ushort(__float2bfloat16(a[k] - __bfloat162float(hb)));
    }
    *(uint2*)&g_Whi[base + i] = make_uint2(h[0] | ((uint32_t)h[1]<<16), h[2] | ((uint32_t)h[3]<<16));
    *(uint2*)&g_Wlo[base + i] = make_uint2(l[0] | ((uint32_t)l[1]<<16), l[2] | ((uint32_t)l[3]<<16));
}

// ---------------------------------------------------------------------------
// qkvmm: HMMA QKV projection. out[m][e] = sum_d x[m][d] W[e][d] + b[e].
// CTA = 128 m-rows x 256 e (4 e-tiles of 64), 8 warps (warp = 16 rows x 64 e).
// 3-term bf16 split; bias in fp32; writes hi/lo bf16 directly.
// ---------------------------------------------------------------------------
__global__ __launch_bounds__(256, 1)
void qkvmm_kernel(const float* __restrict__ bq, const float* __restrict__ bk,
                  const float* __restrict__ bv)
{
    extern __shared__ char sm[];
    uint32_t sb = smem_u32(sm);
    const int t = threadIdx.x, lane = t & 31, wid = t >> 5;
    const int z = blockIdx.x;
    const int m0 = blockIdx.y * 128;
    const float* bias = (z == 0) ? bq : (z == 1) ? bk : bv;
    __nv_bfloat16* ohi = (z == 0) ? g_Qhi : (z == 1) ? g_Khi : g_Vhi;
    __nv_bfloat16* olo = (z == 0) ? g_Qlo : (z == 1) ? g_Klo : g_Vlo;
    const char* xh = (const char*)g_xhi + (size_t)m0 * 512;
    const char* xl = (const char*)g_xlo + (size_t)m0 * 512;
    const char* wh = (const char*)g_Whi + (size_t)z * 131072;
    const char* wl = (const char*)g_Wlo + (size_t)z * 131072;

    // x tile 128 x 512B hi/lo -> smem (once)
    #pragma unroll
    for (int i = 0; i < 16; i++) {
        int id = i*256 + t;           // 4096 chunks
        int row = id >> 5, cb = (id & 31) * 16;
        uint32_t o = xswz(row, cb);
        *(uint4*)(sm + SMX_H + o) = *(const uint4*)(xh + (size_t)row*512 + cb);
        *(uint4*)(sm + SMX_L + o) = *(const uint4*)(xl + (size_t)row*512 + cb);
    }

    const int lrow = lane & 15, lk16 = (lane >> 4) * 16;
    const int wrow = (lane >> 4) * 8 + (lane & 7);
    const int kb16 = ((lane >> 3) & 1) * 16;
    const int g = lane >> 2, tq = lane & 3;

    for (int et = 0; et < 4; et++) {
        __syncthreads();   // x load (et=0) / previous compute done
        // W tile 64 x 512B hi/lo
        const char* wph = wh + (size_t)et * 64 * 512;
        const char* wpl = wl + (size_t)et * 64 * 512;
        #pragma unroll
        for (int i = 0; i < 8; i++) {
            int id = i*256 + t;       // 2048 chunks
            int row = id >> 5, cb = (id & 31) * 16;
            uint32_t o = qswz(row, cb);
            *(uint4*)(sm + SMW_H + o) = *(const uint4*)(wph + (size_t)row*512 + cb);
            *(uint4*)(sm + SMW_L + o) = *(const uint4*)(wpl + (size_t)row*512 + cb);
        }
        __syncthreads();

        float acc[8][4] = {};
        #pragma unroll
        for (int ks = 0; ks < 16; ks++) {
            uint32_t axh[4], axl[4];
            uint32_t xo = xswz(16*wid + lrow, ks*32 + lk16);
            ldsm4(axh, sb + SMX_H + xo);
            ldsm4(axl, sb + SMX_L + xo);
            #pragma unroll
            for (int n16 = 0; n16 < 4; n16++) {
                uint32_t bwh[4], bwl[4];
                uint32_t wo = qswz(n16*16 + wrow, ks*32 + kb16);
                ldsm4(bwh, sb + SMW_H + wo);
                ldsm4(bwl, sb + SMW_L + wo);
                mma16816(acc[n16*2],   axh, bwh);
                mma16816(acc[n16*2],   axh, bwl);
                mma16816(acc[n16*2],   axl, bwh);
                mma16816(acc[n16*2+1], axh, bwh + 2);
                mma16816(acc[n16*2+1], axh, bwl + 2);
                mma16816(acc[n16*2+1], axl, bwh + 2);
            }
        }

        // epilogue: bias, split hi/lo, store
        size_t row0 = (size_t)(m0 + 16*wid + g);
        #pragma unroll
        for (int n2 = 0; n2 < 8; n2++) {
            int col = et*64 + n2*8 + 2*tq;
            float b0 = bias[col], b1 = bias[col + 1];
            float v00 = acc[n2][0] + b0, v01 = acc[n2][1] + b1;
            float v10 = acc[n2][2] + b0, v11 = acc[n2][3] + b1;
            __nv_bfloat16 h00 = __float2bfloat16(v00), h01 = __float2bfloat16(v01);
            __nv_bfloat16 h10 = __float2bfloat16(v10), h11 = __float2bfloat16(v11);
            uint32_t hw0 = __bfloat16_as_ushort(h00) | ((uint32_t)__bfloat16_as_ushort(h01) << 16);
            uint32_t hw1 = __bfloat16_as_ushort(h10) | ((uint32_t)__bfloat16_as_ushort(h11) << 16);
            ushort l00 = __bfloat16_as_ushort(__float2bfloat16(v00 - __bfloat162float(h00)));
            ushort l01 = __bfloat16_as_ushort(__float2bfloat16(v01 - __bfloat162float(h01)));
            ushort l10 = __bfloat16_as_ushort(__float2bfloat16(v10 - __bfloat162float(h10)));
            ushort l11 = __bfloat16_as_ushort(__float2bfloat16(v11 - __bfloat162float(h11)));
            uint32_t lw0 = l00 | ((uint32_t)l01 << 16);
            uint32_t lw1 = l10 | ((uint32_t)l11 << 16);
            *(uint32_t*)&ohi[row0*Dd + col]       = hw0;
            *(uint32_t*)&olo[row0*Dd + col]       = lw0;
            *(uint32_t*)&ohi[(row0 + 8)*Dd + col] = hw1;
            *(uint32_t*)&olo[(row0 + 8)*Dd + col] = lw1;
        }
    }
}

// ---------------------------------------------------------------------------
// HMMA flash attention (byte-identical to the 870 µs R8 kernel)
// ---------------------------------------------------------------------------
__global__ __launch_bounds__(256, 1)
void attn_kernel(const int* __restrict__ mask, float* __restrict__ out)
{
    extern __shared__ char sm[];
    uint32_t sb = smem_u32(sm);
    const int t = threadIdx.x, lane = t & 31, wid = t >> 5;
    const int r = wid & 3, cw = wid >> 2;
    const int b = blockIdx.y, q0 = blockIdx.x * 64;
    const int g = lane >> 2, tq = lane & 3;
    const int lrow = lane & 15, lk16 = (lane >> 4) * 16;

    {
        const char* qh = (const char*)&g_Qhi[(size_t)(b*Nn + q0)*Dd];
        const char* ql = (const char*)&g_Qlo[(size_t)(b*Nn + q0)*Dd];
        #pragma unroll
        for (int i = 0; i < 8; i++) {
            int id = i*256 + t;
            int row = id >> 5, cb = (id & 31) * 16;
            uint32_t o = qswz(row, cb);
            *(uint4*)(sm + SM_QH + o) = *(const uint4*)(qh + (size_t)row*512 + cb);
            *(uint4*)(sm + SM_QL + o) = *(const uint4*)(ql + (size_t)row*512 + cb);
        }
    }

    const char* baseKh = (const char*)&g_Khi[(size_t)(b*Nn)*Dd];
    const char* baseKl = (const char*)&g_Klo[(size_t)(b*Nn)*Dd];
    const char* baseVh = (const char*)&g_Vhi[(size_t)(b*Nn)*Dd];
    const char* baseVl = (const char*)&g_Vlo[(size_t)(b*Nn)*Dd];
    auto issue = [&](int jt) {
        uint32_t stg = sb + SM_ST + (jt & 1) * 65536;
        size_t gb = (size_t)(jt * 32) * 512;
        const char* srcs[4] = { baseKh + gb, baseKl + gb, baseVh + gb, baseVl + gb };
        #pragma unroll
        for (int a = 0; a < 4; a++) {
            #pragma unroll
            for (int i = 0; i < 4; i++) {
                int id = i*256 + t;
                int row = id >> 5, cb = (id & 31) * 16;
                CPA16(stg + a*16384 + kswz(row, cb), srcs[a] + (size_t)row*512 + cb);
            }
        }
    };
    issue(0); CPCOMMIT();
    issue(1); CPCOMMIT();
    __syncthreads();

    float l0 = 0.f, l1 = 0.f;
    float o[16][4] = {};

    for (int j = 0; j < 128; j++) {
        CPWAIT1();
        __syncthreads();
        uint32_t stg = sb + SM_ST + (j & 1) * 65536;
        uint32_t sKh = stg, sKl = stg + 16384, sVh = stg + 32768, sVl = stg + 49152;

        const int j0 = j * 32;
        const int* mrow = mask + (size_t)(b*Nn + q0 + 16*r + g) * Nn + j0 + 16*cw + 2*tq;
        int2 mA0 = *(const int2*)mrow;
        int2 mA1 = *(const int2*)(mrow + 8);
        int2 mB0 = *(const int2*)(mrow + 8*Nn);
        int2 mB1 = *(const int2*)(mrow + 8*Nn + 8);

        float s_hh[2][4] = {}, s_hl[2][4] = {}, s_lh[2][4] = {};
        const int key = 16*cw + (lane >> 4)*8 + (lane & 7);
        const int kb16 = ((lane >> 3) & 1) * 16;
        #pragma unroll
        for (int ks = 0; ks < 16; ks++) {
            uint32_t aqh[4], aql[4], bk[4], bl[4];
            uint32_t qo = ks*32 + lk16;
            ldsm4(aqh, sb + SM_QH + qswz(16*r + lrow, qo));
            ldsm4(aql, sb + SM_QL + qswz(16*r + lrow, qo));
            uint32_t ko = kswz(key, ks*32 + kb16);
            ldsm4(bk, sKh + ko);
            ldsm4(bl, sKl + ko);
            mma16816(s_hh[0], aqh, bk);
            mma16816(s_hl[0], aqh, bl);
            mma16816(s_lh[0], aql, bk);
            mma16816(s_hh[1], aqh, bk + 2);
            mma16816(s_hl[1], aqh, bl + 2);
            mma16816(s_lh[1], aql, bk + 2);
        }
        float sa[2][4];
        #pragma unroll
        for (int h = 0; h < 2; h++)
            #pragma unroll
            for (int e = 0; e < 4; e++)
                sa[h][e] = s_hh[h][e] + s_hl[h][e] + s_lh[h][e];

        {
            const float sc = 0.0625f;
            float p00 = mA0.x ? __expf(sa[0][0]*sc) : 0.f;
            float p01 = mA0.y ? __expf(sa[0][1]*sc) : 0.f;
            float p02 = mB0.x ? __expf(sa[0][2]*sc) : 0.f;
            float p03 = mB0.y ? __expf(sa[0][3]*sc) : 0.f;
            float p10 = mA1.x ? __expf(sa[1][0]*sc) : 0.f;
            float p11 = mA1.y ? __expf(sa[1][1]*sc) : 0.f;
            float p12 = mB1.x ? __expf(sa[1][2]*sc) : 0.f;
            float p13 = mB1.y ? __expf(sa[1][3]*sc) : 0.f;
            l0 += p00 + p01 + p10 + p11;
            l1 += p02 + p03 + p12 + p13;
            int colb = (16*cw + 2*tq) * 2;
            int row0 = 16*r + g;
            #pragma unroll
            for (int nt = 0; nt < 2; nt++) {
                float pa = nt ? p10 : p00, pb = nt ? p11 : p01;
                float pc = nt ? p12 : p02, pd = nt ? p13 : p03;
                uint32_t phT = __bfloat16_as_ushort(__float2bfloat16(pa))
                             | ((uint32_t)__bfloat16_as_ushort(__float2bfloat16(pb)) << 16);
                uint32_t phB = __bfloat16_as_ushort(__float2bfloat16(pc))
                             | ((uint32_t)__bfloat16_as_ushort(__float2bfloat16(pd)) << 16);
                int cb2 = colb + nt*16;
                *(uint32_t*)(sm + SM_PH + pswz(row0,     cb2)) = phT;
                *(uint32_t*)(sm + SM_PH + pswz(row0 + 8, cb2)) = phB;
            }
        }
        __syncthreads();

        const int vr = (lane & 7) + ((lane >> 3) & 1) * 8;
        #pragma unroll
        for (int ks = 0; ks < 2; ks++) {
            uint32_t aph[4];
            ldsm4(aph, sb + SM_PH + pswz(16*r + lrow, ks*32 + lk16));
            #pragma unroll
            for (int n2 = 0; n2 < 8; n2++) {
                int vcb = (128*cw + n2*16 + (lane >> 4)*8) * 2;
                uint32_t vo = kswz(ks*16 + vr, vcb);
                uint32_t bvh[4], bvl[4];
                ldsm4t(bvh, sVh + vo);
                ldsm4t(bvl, sVl + vo);
                mma16816(o[n2*2],   aph, bvh);
                mma16816(o[n2*2],   aph, bvl);
                mma16816(o[n2*2+1], aph, bvh + 2);
                mma16816(o[n2*2+1], aph, bvl + 2);
            }
        }
        __syncthreads();
        if (j + 2 < 128) issue(j + 2);
        CPCOMMIT();
    }

    l0 += __shfl_xor_sync(0xffffffffu, l0, 1);
    l0 += __shfl_xor_sync(0xffffffffu, l0, 2);
    l1 += __shfl_xor_sync(0xffffffffu, l1, 1);
    l1 += __shfl_xor_sync(0xffffffffu, l1, 2);
    float* Ls = (float*)(sm + SM_PH);
    if (tq == 0) {
        Ls[cw*64 + 16*r + g]     = l0;
        Ls[cw*64 + 16*r + 8 + g] = l1;
    }
    __syncthreads();
    float inv0 = 1.0f / (Ls[16*r + g]     + Ls[64 + 16*r + g]);
    float inv1 = 1.0f / (Ls[16*r + 8 + g] + Ls[64 + 16*r + 8 + g]);
    size_t row0 = (size_t)(b*Nn + q0 + 16*r + g);
    #pragma unroll
    for (int nt = 0; nt < 16; nt++) {
        int col = 128*cw + nt*8 + 2*tq;
        *(float2*)&out[row0*Dd + col]       = make_float2(o[nt][0]*inv0, o[nt][1]*inv0);
        *(float2*)&out[(row0 + 8)*Dd + col] = make_float2(o[nt][2]*inv1, o[nt][3]*inv1);
    }
}

extern "C" void kernel_launch(void* const* d_in, const int* in_sizes, int n_in,
                              void* d_out, int out_size)
{
    const float* x    = (const float*)d_in[0];
    const int*   mask = (const int*)  d_in[1];
    const float* Wq   = (const float*)d_in[2];
    const float* bq   = (const float*)d_in[3];
    const float* Wk   = (const float*)d_in[4];
    const float* bk   = (const float*)d_in[5];
    const float* Wv   = (const float*)d_in[6];
    const float* bv   = (const float*)d_in[7];
    float* out = (float*)d_out;

    cudaFuncSetAttribute(attn_kernel,
                         cudaFuncAttributeMaxDynamicSharedMemorySize, SM_TOT);
    cudaFuncSetAttribute(qkvmm_kernel,
                         cudaFuncAttributeMaxDynamicSharedMemorySize, SM_QKV_TOT);

    convX_kernel<<<Mm*Dd/1024, 256>>>(x);
    dim3 gW(Dd*Dd/1024, 3);
    convW_kernel<<<gW, 256>>>(Wq, Wk, Wv);
    dim3 gM(3, Mm/128);
    qkvmm_kernel<<<gM, 256, SM_QKV_TOT>>>(bq, bk, bv);
    dim3 g2(Nn/64, Bb);
    attn_kernel<<<g2, 256, SM_TOT>>>(mask, out);
}